// round 5
// baseline (speedup 1.0000x reference)
#include <cuda_runtime.h>
#include <math.h>

#define BQ 65536
#define NN 100000
#define KH 20
#define HD 128
#define INV_SQRT_H 0.08838834764831845f

typedef unsigned long long u64;

// ---------------- scratch ----------------
__device__ float g_w2t[HD * HD];
__device__ float g_wq[NN * HD];
__device__ float g_zpart[2 * BQ * HD];
__device__ float g_hbar[2 * BQ * HD];
__device__ float g_zfull[2 * BQ * HD];

// ---------------- f32x2 helpers ----------------
__device__ __forceinline__ u64 pack2(float lo, float hi) {
    u64 r; asm("mov.b64 %0,{%1,%2};" : "=l"(r) : "f"(lo), "f"(hi)); return r;
}
__device__ __forceinline__ u64 rep2(float v) { return pack2(v, v); }
__device__ __forceinline__ void unpack2(u64 p, float& lo, float& hi) {
    asm("mov.b64 {%0,%1},%2;" : "=f"(lo), "=f"(hi) : "l"(p));
}
__device__ __forceinline__ u64 ffma2(u64 a, u64 b, u64 c) {
    u64 d; asm("fma.rn.f32x2 %0,%1,%2,%3;" : "=l"(d) : "l"(a), "l"(b), "l"(c)); return d;
}
__device__ __forceinline__ u64 fadd2(u64 a, u64 b) {
    u64 d; asm("add.rn.f32x2 %0,%1,%2;" : "=l"(d) : "l"(a), "l"(b)); return d;
}
__device__ __forceinline__ float hsum2(u64 p) {
    float lo, hi; unpack2(p, lo, hi); return lo + hi;
}
__device__ __forceinline__ float warp_sum(float v) {
    #pragma unroll
    for (int off = 16; off; off >>= 1) v += __shfl_xor_sync(0xffffffffu, v, off);
    return v;
}

// ---------------- kernel 0: transpose tp_w2 ----------------
__global__ void transpose128_kernel(const float* __restrict__ W) {
    int d = blockIdx.x, h = threadIdx.x;
    g_w2t[d * HD + h] = W[h * HD + d];
}

// ---------------- GEMM core (f32x2): C[M,128] = A[M,128]@B[128,128] ----------------
// 256 threads, tile 64(M) x 128(N), k-chunks of 32.
// As2: A tile staged as REPLICATED pairs (a,a), layout [row][k] stride 34 u64.
// thread (mt=tid>>5, nt=tid&31) owns rows mt*8..+7, col-pairs (nt*4,nt*4+1),(nt*4+2,nt*4+3).
#define AS2_STRIDE 34

__device__ __forceinline__ void gemm128_core_x2(
    const float* __restrict__ A, const float* __restrict__ Bm, int M,
    u64* As2, float* Bs, u64 acc[8][2])
{
    int tid = threadIdx.x;
    int nt = tid & 31, mt = tid >> 5;
    int m0 = blockIdx.x * 64;

    for (int k0 = 0; k0 < 128; k0 += 32) {
        // stage A tile [64 rows][32 k] replicated
        #pragma unroll
        for (int t = 0; t < 2; t++) {
            int idx = tid + t * 256;            // [0,512)
            int row = idx >> 3;
            int kk  = (idx & 7) << 2;
            float4 v = make_float4(0.f, 0.f, 0.f, 0.f);
            if (m0 + row < M)
                v = *(const float4*)(A + (size_t)(m0 + row) * HD + k0 + kk);
            ulonglong2* dst = (ulonglong2*)&As2[row * AS2_STRIDE + kk];
            dst[0] = make_ulonglong2(rep2(v.x), rep2(v.y));
            dst[1] = make_ulonglong2(rep2(v.z), rep2(v.w));
        }
        // stage B tile [32 k][128 n]
        #pragma unroll
        for (int t = 0; t < 4; t++) {
            int idx = tid + t * 256;            // [0,1024)
            int row = idx >> 5;
            int nq  = (idx & 31) << 2;
            *(float4*)(Bs + row * HD + nq) =
                *(const float4*)(Bm + (size_t)(k0 + row) * HD + nq);
        }
        __syncthreads();

        #pragma unroll
        for (int k2 = 0; k2 < 16; k2++) {
            int k = k2 * 2;
            ulonglong2 b0 = *(const ulonglong2*)(Bs + k * HD + nt * 4);
            ulonglong2 b1 = *(const ulonglong2*)(Bs + (k + 1) * HD + nt * 4);
            #pragma unroll
            for (int r = 0; r < 8; r++) {
                ulonglong2 a = *(const ulonglong2*)&As2[(mt * 8 + r) * AS2_STRIDE + k];
                acc[r][0] = ffma2(a.x, b0.x, acc[r][0]);
                acc[r][1] = ffma2(a.x, b0.y, acc[r][1]);
                acc[r][0] = ffma2(a.y, b1.x, acc[r][0]);
                acc[r][1] = ffma2(a.y, b1.y, acc[r][1]);
            }
        }
        __syncthreads();
    }
}

// ---------------- kernel 1: g_wq = node_emb @ W2^T ----------------
__global__ __launch_bounds__(256) void gemm_wq_kernel(const float* __restrict__ node_emb) {
    __shared__ u64   As2[64 * AS2_STRIDE];
    __shared__ float Bs[32 * HD];
    u64 acc[8][2];
    #pragma unroll
    for (int r = 0; r < 8; r++) { acc[r][0] = 0; acc[r][1] = 0; }
    gemm128_core_x2(node_emb, g_w2t, NN, As2, Bs, acc);

    int tid = threadIdx.x;
    int nt = tid & 31, mt = tid >> 5;
    int m0 = blockIdx.x * 64;
    #pragma unroll
    for (int r = 0; r < 8; r++) {
        int row = m0 + mt * 8 + r;
        if (row < NN)
            *(ulonglong2*)(g_wq + (size_t)row * HD + nt * 4) =
                make_ulonglong2(acc[r][0], acc[r][1]);
    }
}

// ---------------- kernel 3: g_zfull = g_hbar @ W2 + g_zpart + b2 ----------------
__global__ __launch_bounds__(256) void gemm_ztime_kernel(const float* __restrict__ tp_w2,
                                                         const float* __restrict__ tp_b2) {
    __shared__ u64   As2[64 * AS2_STRIDE];
    __shared__ float Bs[32 * HD];
    u64 acc[8][2];
    #pragma unroll
    for (int r = 0; r < 8; r++) { acc[r][0] = 0; acc[r][1] = 0; }
    gemm128_core_x2(g_hbar, tp_w2, 2 * BQ, As2, Bs, acc);

    int tid = threadIdx.x;
    int nt = tid & 31, mt = tid >> 5;
    int m0 = blockIdx.x * 64;
    ulonglong2 bb = *(const ulonglong2*)(tp_b2 + nt * 4);
    #pragma unroll
    for (int r = 0; r < 8; r++) {
        int row = m0 + mt * 8 + r;
        ulonglong2 z = *(const ulonglong2*)(g_zpart + (size_t)row * HD + nt * 4);
        u64 c0 = fadd2(fadd2(acc[r][0], z.x), bb.x);
        u64 c1 = fadd2(fadd2(acc[r][1], z.y), bb.y);
        *(ulonglong2*)(g_zfull + (size_t)row * HD + nt * 4) = make_ulonglong2(c0, c1);
    }
}

// ---------------- kernel 2: attention (warp per edge-side) ----------------
__global__ __launch_bounds__(128) void attn_kernel(
    const int* __restrict__ edge_index, const int* __restrict__ edge_ts,
    const int* __restrict__ h_nb, const int* __restrict__ h_tm, const int* __restrict__ h_sg,
    const float* __restrict__ node_emb, const float* __restrict__ sign_emb,
    const float* __restrict__ tp_w1, const float* __restrict__ tp_b1,
    const float* __restrict__ tp_b2)
{
    __shared__ float sp[4][KH * 36];     // per-warp score partials [k][lane]
    __shared__ int4  smeta[4][KH];       // per-k: {pk, delta_bits, a_bits, pad}

    int w    = threadIdx.x >> 5;
    int lane = threadIdx.x & 31;
    int wid  = blockIdx.x * 4 + w;       // edge-side id in [0, 2B)
    int e    = wid & (BQ - 1);
    int side = wid >> 16;
    int node = edge_index[side * BQ + e];
    int qt   = edge_ts[e];

    const ulonglong2* ne8 = (const ulonglong2*)node_emb;
    ulonglong2 q   = ne8[(size_t)node * 32 + lane];
    ulonglong2 wq  = ((const ulonglong2*)g_wq)[(size_t)node * 32 + lane];
    float4 w1  = ((const float4*)tp_w1)[lane];
    float4 b1  = ((const float4*)tp_b1)[lane];
    ulonglong2 s0  = ((const ulonglong2*)sign_emb)[lane];
    ulonglong2 s1  = ((const ulonglong2*)sign_emb)[32 + lane];
    ulonglong2 b2v = ((const ulonglong2*)tp_b2)[lane];

    float qs0 = warp_sum(hsum2(ffma2(q.x, s0.x, ffma2(q.y, s0.y, 0ULL))));
    float qs1 = warp_sum(hsum2(ffma2(q.x, s1.x, ffma2(q.y, s1.y, 0ULL))));
    float qb2 = warp_sum(hsum2(ffma2(q.x, b2v.x, ffma2(q.y, b2v.y, 0ULL))));

    // per-k metadata, one k per lane (<20)
    int   sg_l = 0;
    bool  valid_l = false;
    if (lane < KH) {
        int nb = h_nb[(size_t)node * KH + lane];
        int tm = h_tm[(size_t)node * KH + lane];
        sg_l   = h_sg[(size_t)node * KH + lane] & 1;
        valid_l = (nb != -1) && (tm < qt);
        int nbc = (nb == -1) ? 0 : nb;
        unsigned pk = ((unsigned)nbc << 1) | (unsigned)sg_l | (valid_l ? 0u : 0x80000000u);
        float delta = (float)qt - (float)tm;
        *(int2*)&smeta[w][lane] = make_int2((int)pk, __float_as_int(delta));
    }
    __syncwarp();

    // pass 1: gathers + score partials
    ulonglong2 nek[KH];
    #pragma unroll
    for (int k = 0; k < KH; k++) {
        int2 md = *(const int2*)&smeta[w][k];
        unsigned pk = (unsigned)md.x;
        float delta = __int_as_float(md.y);
        int nbc = (int)((pk >> 1) & 0x3FFFFFFFu);
        ulonglong2 ne = ne8[(size_t)nbc * 32 + lane];
        nek[k] = ne;
        float hx = fmaxf(fmaf(delta, w1.x, b1.x), 0.f);
        float hy = fmaxf(fmaf(delta, w1.y, b1.y), 0.f);
        float hz = fmaxf(fmaf(delta, w1.z, b1.z), 0.f);
        float hw = fmaxf(fmaf(delta, w1.w, b1.w), 0.f);
        u64 h01 = pack2(hx, hy), h23 = pack2(hz, hw);
        u64 pa = ffma2(q.x, ne.x,
                 ffma2(q.y, ne.y,
                 ffma2(h01, wq.x,
                 ffma2(h23, wq.y, 0ULL))));
        sp[w][k * 36 + lane] = hsum2(pa);
    }
    __syncwarp();

    // per-k total + softmax (lane k owns score k)
    float sc = -3.0e38f;
    if (lane < KH) {
        const float* row = &sp[w][lane * 36];
        float s = 0.f;
        #pragma unroll
        for (int j = 0; j < 8; j++) {
            float4 v = *(const float4*)(row + j * 4);
            s += v.x + v.y + v.z + v.w;
        }
        float csg = (sg_l ? qs1 : qs0) + qb2;
        sc = valid_l ? (s + csg) * INV_SQRT_H : -1e9f;
    }
    float m = sc;
    #pragma unroll
    for (int off = 16; off; off >>= 1) m = fmaxf(m, __shfl_xor_sync(0xffffffffu, m, off));
    float ee = __expf(sc - m);               // lanes>=20 -> exp(~-3e38) = 0
    float ssum = warp_sum(ee);
    float a = ee / ssum;
    if (lane < KH) smeta[w][lane].z = __float_as_int(a);
    __syncwarp();

    // pass 2: weighted accumulation
    u64 z0 = 0, z1 = 0, hb0 = 0, hb1 = 0;
    #pragma unroll
    for (int k = 0; k < KH; k++) {
        int4 md = smeta[w][k];
        unsigned pk = (unsigned)md.x;
        float delta = __int_as_float(md.y);
        u64 ar = rep2(__int_as_float(md.z));
        ulonglong2 ne = nek[k];
        ulonglong2 se = (pk & 1u) ? s1 : s0;
        z0 = ffma2(ar, fadd2(ne.x, se.x), z0);
        z1 = ffma2(ar, fadd2(ne.y, se.y), z1);
        float hx = fmaxf(fmaf(delta, w1.x, b1.x), 0.f);
        float hy = fmaxf(fmaf(delta, w1.y, b1.y), 0.f);
        float hz = fmaxf(fmaf(delta, w1.z, b1.z), 0.f);
        float hw = fmaxf(fmaf(delta, w1.w, b1.w), 0.f);
        hb0 = ffma2(ar, pack2(hx, hy), hb0);
        hb1 = ffma2(ar, pack2(hz, hw), hb1);
    }
    ((ulonglong2*)g_zpart)[(size_t)wid * 32 + lane] = make_ulonglong2(z0, z1);
    ((ulonglong2*)g_hbar )[(size_t)wid * 32 + lane] = make_ulonglong2(hb0, hb1);
}

// ---------------- kernel 4: feat build + classifier GEMM + epilogue ----------------
__global__ __launch_bounds__(256) void classifier_kernel(
    const float* __restrict__ em_w1, const float* __restrict__ em_b1,
    const float* __restrict__ em_w2, const float* __restrict__ em_b2,
    float* __restrict__ out)
{
    __shared__ u64   As2[64 * AS2_STRIDE];
    __shared__ float Bs[32 * HD];
    int tid = threadIdx.x;
    int nt = tid & 31, mt = tid >> 5;
    int e0 = blockIdx.x * 64;
    const float4* Z4 = (const float4*)g_zfull;

    u64 acc[8][2];
    #pragma unroll
    for (int r = 0; r < 8; r++) { acc[r][0] = 0; acc[r][1] = 0; }

    for (int c = 0; c < 16; c++) {
        int k0  = c * 32;
        int sel = k0 >> 7;
        int j0  = k0 & 127;
        // stage feat tile [64 rows][32 k] replicated
        #pragma unroll
        for (int t = 0; t < 2; t++) {
            int idx = tid + t * 256;
            int row = idx >> 3;
            int kk  = (idx & 7) << 2;
            int j   = j0 + kk;
            int e   = e0 + row;
            float4 zu = Z4[(size_t)e * 32 + (j >> 2)];
            float4 zv = Z4[(size_t)(BQ + e) * 32 + (j >> 2)];
            float4 v;
            if      (sel == 0) v = zu;
            else if (sel == 1) v = zv;
            else if (sel == 2) v = make_float4(fabsf(zu.x - zv.x), fabsf(zu.y - zv.y),
                                               fabsf(zu.z - zv.z), fabsf(zu.w - zv.w));
            else               v = make_float4(zu.x * zv.x, zu.y * zv.y,
                                               zu.z * zv.z, zu.w * zv.w);
            ulonglong2* dst = (ulonglong2*)&As2[row * AS2_STRIDE + kk];
            dst[0] = make_ulonglong2(rep2(v.x), rep2(v.y));
            dst[1] = make_ulonglong2(rep2(v.z), rep2(v.w));
        }
        // stage em_w1 rows k0..k0+31
        #pragma unroll
        for (int t = 0; t < 4; t++) {
            int idx = tid + t * 256;
            int row = idx >> 5;
            int nq  = (idx & 31) << 2;
            *(float4*)(Bs + row * HD + nq) =
                *(const float4*)(em_w1 + (size_t)(k0 + row) * HD + nq);
        }
        __syncthreads();

        #pragma unroll
        for (int k2 = 0; k2 < 16; k2++) {
            int k = k2 * 2;
            ulonglong2 b0 = *(const ulonglong2*)(Bs + k * HD + nt * 4);
            ulonglong2 b1 = *(const ulonglong2*)(Bs + (k + 1) * HD + nt * 4);
            #pragma unroll
            for (int r = 0; r < 8; r++) {
                ulonglong2 a = *(const ulonglong2*)&As2[(mt * 8 + r) * AS2_STRIDE + k];
                acc[r][0] = ffma2(a.x, b0.x, acc[r][0]);
                acc[r][1] = ffma2(a.x, b0.y, acc[r][1]);
                acc[r][0] = ffma2(a.y, b1.x, acc[r][0]);
                acc[r][1] = ffma2(a.y, b1.y, acc[r][1]);
            }
        }
        __syncthreads();
    }

    // epilogue: relu + dot with em_w2, warp-reduce per row
    float4 b1e = *(const float4*)(em_b1 + nt * 4);
    float4 w2e = *(const float4*)(em_w2 + nt * 4);
    float  eb2 = em_b2[0];
    #pragma unroll
    for (int r = 0; r < 8; r++) {
        float a0, a1, a2, a3;
        unpack2(acc[r][0], a0, a1);
        unpack2(acc[r][1], a2, a3);
        float p = fmaxf(a0 + b1e.x, 0.f) * w2e.x
                + fmaxf(a1 + b1e.y, 0.f) * w2e.y
                + fmaxf(a2 + b1e.z, 0.f) * w2e.z
                + fmaxf(a3 + b1e.w, 0.f) * w2e.w;
        p = warp_sum(p);
        if (nt == 0) out[e0 + mt * 8 + r] = p + eb2;
    }
}

// ---------------- launch ----------------
extern "C" void kernel_launch(void* const* d_in, const int* in_sizes, int n_in,
                              void* d_out, int out_size) {
    const int*   edge_index = (const int*)d_in[0];
    const int*   edge_ts    = (const int*)d_in[1];
    const int*   h_nb       = (const int*)d_in[2];
    const int*   h_tm       = (const int*)d_in[3];
    const int*   h_sg       = (const int*)d_in[4];
    const float* node_emb   = (const float*)d_in[5];
    const float* sign_emb   = (const float*)d_in[6];
    const float* tp_w1      = (const float*)d_in[7];
    const float* tp_b1      = (const float*)d_in[8];
    const float* tp_w2      = (const float*)d_in[9];
    const float* tp_b2      = (const float*)d_in[10];
    const float* em_w1      = (const float*)d_in[11];
    const float* em_b1      = (const float*)d_in[12];
    const float* em_w2      = (const float*)d_in[13];
    const float* em_b2      = (const float*)d_in[14];
    float* out = (float*)d_out;

    transpose128_kernel<<<HD, HD>>>(tp_w2);
    gemm_wq_kernel<<<(NN + 63) / 64, 256>>>(node_emb);
    attn_kernel<<<(2 * BQ) / 4, 128>>>(edge_index, edge_ts, h_nb, h_tm, h_sg,
                                       node_emb, sign_emb, tp_w1, tp_b1, tp_b2);
    gemm_ztime_kernel<<<(2 * BQ) / 64, 256>>>(tp_w2, tp_b2);
    classifier_kernel<<<BQ / 64, 256>>>(em_w1, em_b1, em_w2, em_b2, out);
}